// round 6
// baseline (speedup 1.0000x reference)
#include <cuda_runtime.h>
#include <cstdint>

#define BATCHN 8
#define TT 2048
#define EE 1024
#define DD 128
#define MTOT (BATCHN*TT)

// Scratch for Q,K,V projections (8 MB each) — __device__ globals per allocation rules.
__device__ float g_q[MTOT*DD];
__device__ float g_k[MTOT*DD];
__device__ float g_v[MTOT*DD];

typedef unsigned long long ull;

__device__ __forceinline__ ull packf2(float x, float y) {
  ull r;
  asm("mov.b64 %0, {%1, %2};" : "=l"(r) : "f"(x), "f"(y));
  return r;
}
__device__ __forceinline__ void fma2(ull& c, ull a, ull b) {
  asm("fma.rn.f32x2 %0, %1, %2, %0;" : "+l"(c) : "l"(a), "l"(b));
}
union F2U { ull u; float2 f; };

// ---------------------------------------------------------------------------
// QKV projection (unchanged — measured at the scalar FFMA roofline, ~350us).
// ---------------------------------------------------------------------------
__global__ __launch_bounds__(256) void qkv_gemm_kernel(
    const float* __restrict__ X, const float* __restrict__ Wq,
    const float* __restrict__ Wk, const float* __restrict__ Wv) {
  __shared__ float Xs[8][128];
  __shared__ float Ws[8][128];
  const int which = blockIdx.y;
  const float* __restrict__ W = (which == 0) ? Wq : (which == 1) ? Wk : Wv;
  float* __restrict__ outp = (which == 0) ? g_q : (which == 1) ? g_k : g_v;

  const int m0 = blockIdx.x * 128;
  const int tid = threadIdx.x;
  const int tm = tid >> 4;
  const int tn = tid & 15;
  const int xm = tid >> 1;
  const int xk = (tid & 1) << 2;
  const int wk = tid >> 5;
  const int wn = (tid & 31) << 2;

  ull acc2[8][4];
#pragma unroll
  for (int i = 0; i < 8; i++)
#pragma unroll
    for (int j = 0; j < 4; j++) acc2[i][j] = 0ull;

  for (int k0 = 0; k0 < EE; k0 += 8) {
    float4 xv = *(const float4*)&X[(size_t)(m0 + xm) * EE + k0 + xk];
    float4 wv = *(const float4*)&W[(size_t)(k0 + wk) * DD + wn];
    __syncthreads();
    Xs[xk + 0][xm] = xv.x;
    Xs[xk + 1][xm] = xv.y;
    Xs[xk + 2][xm] = xv.z;
    Xs[xk + 3][xm] = xv.w;
    *(float4*)&Ws[wk][wn] = wv;
    __syncthreads();
#pragma unroll
    for (int kk = 0; kk < 8; kk++) {
      float a[8];
      *(float4*)&a[0] = *(const float4*)&Xs[kk][tm * 8];
      *(float4*)&a[4] = *(const float4*)&Xs[kk][tm * 8 + 4];
      ulonglong2 b01 = *(const ulonglong2*)&Ws[kk][tn * 8];
      ulonglong2 b23 = *(const ulonglong2*)&Ws[kk][tn * 8 + 4];
#pragma unroll
      for (int i = 0; i < 8; i++) {
        ull aa = packf2(a[i], a[i]);
        fma2(acc2[i][0], aa, b01.x);
        fma2(acc2[i][1], aa, b01.y);
        fma2(acc2[i][2], aa, b23.x);
        fma2(acc2[i][3], aa, b23.y);
      }
    }
  }

#pragma unroll
  for (int i = 0; i < 8; i++) {
    size_t row = (size_t)(m0 + tm * 8 + i);
    F2U u0, u1, u2, u3;
    u0.u = acc2[i][0]; u1.u = acc2[i][1];
    u2.u = acc2[i][2]; u3.u = acc2[i][3];
    float4 o0 = make_float4(u0.f.x, u0.f.y, u1.f.x, u1.f.y);
    float4 o1 = make_float4(u2.f.x, u2.f.y, u3.f.x, u3.f.y);
    *(float4*)&outp[row * DD + tn * 8] = o0;
    *(float4*)&outp[row * DD + tn * 8 + 4] = o1;
  }
}

// ---------------------------------------------------------------------------
// Causal flash attention v4: broadcast-LDS + register-resident Q/O/softmax.
// 256 threads, 8 warps; warp w owns Q rows 8w..8w+7 of a 64-row block.
// Lane (r=lane&7, c=lane>>3): Q[row][32c..+31] and O[row][32c..+31] in regs.
// K/V smem: chunk-padded (row stride 144, chunk stride 36) so the 4 distinct
// chunk addresses per warp-LDS are bank-disjoint; 8 lanes/chunk broadcast.
// S partials reduced across c via 2x shfl.bfly -> softmax thread-local.
// Double-buffered K/V, register prefetch, ONE barrier per tile.
// Grid (32, 8); qblk = 31-bx (heaviest first for work-stealing balance).
// ---------------------------------------------------------------------------
#define BK 32
#define RSTR 144                 // smem row stride (floats)
#define CSTR 36                  // chunk stride (floats)
#define TILE_F (BK * RSTR)       // 4608 floats per K or V tile
#define BUF_F (2 * TILE_F)       // 9216 floats per buffer (K + V)
#define ATT_SMEM (2 * BUF_F * 4) // 73728 bytes

__global__ __launch_bounds__(256) void attn_kernel(float* __restrict__ out) {
  extern __shared__ float sm_[];

  const int b = blockIdx.y;
  const int qblk = 31 - (int)blockIdx.x;   // heavy CTAs first
  const int tid = threadIdx.x;
  const int w = tid >> 5;
  const int lane = tid & 31;
  const int r = lane & 7;
  const int c = lane >> 3;
  const int row_l = 8 * w + r;             // 0..63
  const int qg = qblk * 64 + row_l;        // global query row (within batch)
  const float scale = 0.08838834764831845f;

  const float* __restrict__ qp = g_q + (size_t)b * TT * DD;
  const float* __restrict__ kp = g_k + (size_t)b * TT * DD;
  const float* __restrict__ vp = g_v + (size_t)b * TT * DD;

  // ---- Q into registers (pre-scaled), held for whole kernel ----
  float q[32];
  {
    const float* qr = &qp[(size_t)qg * DD + 32 * c];
#pragma unroll
    for (int t = 0; t < 8; t++) {
      float4 v = *(const float4*)&qr[4 * t];
      q[4 * t + 0] = v.x * scale;
      q[4 * t + 1] = v.y * scale;
      q[4 * t + 2] = v.z * scale;
      q[4 * t + 3] = v.w * scale;
    }
  }

  float o[32];
#pragma unroll
  for (int i = 0; i < 32; i++) o[i] = 0.f;
  float m = -1e30f, l = 0.f;

  // loader indices: float4 i = tid + it*256 over a 32x128 tile
  const int lj = tid >> 5;        // row within tile (per it: +8)
  const int lq4 = tid & 31;       // float4 index within row
  const int lc = lq4 >> 3;
  const int lt = lq4 & 7;
  const uint32_t soff = (uint32_t)(lj * RSTR + lc * CSTR + lt * 4);

  const int nkt = 2 * qblk + 2;

  // ---- prefetch tile 0 ----
  float4 pre[8];
#pragma unroll
  for (int it = 0; it < 4; it++) {
    pre[it] = *(const float4*)&kp[(size_t)(lj + 8 * it) * DD + lq4 * 4];
    pre[4 + it] = *(const float4*)&vp[(size_t)(lj + 8 * it) * DD + lq4 * 4];
  }

  for (int kt = 0; kt < nkt; kt++) {
    float* buf = sm_ + (kt & 1) * BUF_F;
    // (a) stage prefetched tile
#pragma unroll
    for (int it = 0; it < 4; it++) {
      *(float4*)&buf[soff + 8 * it * RSTR] = pre[it];
      *(float4*)&buf[TILE_F + soff + 8 * it * RSTR] = pre[4 + it];
    }
    // (b) single barrier per tile (double-buffer makes it sufficient)
    __syncthreads();
    // (c) prefetch next tile
    if (kt + 1 < nkt) {
      const size_t krow = (size_t)(kt + 1) * BK;
#pragma unroll
      for (int it = 0; it < 4; it++) {
        pre[it] = *(const float4*)&kp[(krow + lj + 8 * it) * DD + lq4 * 4];
        pre[4 + it] = *(const float4*)&vp[(krow + lj + 8 * it) * DD + lq4 * 4];
      }
    }

    // (d) compute on buf
    const float* Kb = buf + c * CSTR;
    const float* Vb = buf + TILE_F + c * CSTR;

    // ---- S = q . K (partial over this lane's 32-d chunk) ----
    float s[32];
#pragma unroll 4
    for (int j = 0; j < 32; j++) {
      float a0 = 0.f, a1 = 0.f;
#pragma unroll
      for (int t = 0; t < 8; t += 2) {
        float4 k0 = *(const float4*)&Kb[j * RSTR + 4 * t];
        float4 k1 = *(const float4*)&Kb[j * RSTR + 4 * t + 4];
        a0 += q[4 * t + 0] * k0.x + q[4 * t + 1] * k0.y +
              q[4 * t + 2] * k0.z + q[4 * t + 3] * k0.w;
        a1 += q[4 * t + 4] * k1.x + q[4 * t + 5] * k1.y +
              q[4 * t + 6] * k1.z + q[4 * t + 7] * k1.w;
      }
      s[j] = a0 + a1;
    }
    // ---- reduce partials across the 4 d-chunks (lane bits 3,4) ----
#pragma unroll
    for (int j = 0; j < 32; j++) {
      s[j] += __shfl_xor_sync(0xffffffffu, s[j], 8);
      s[j] += __shfl_xor_sync(0xffffffffu, s[j], 16);
    }

    // ---- causal mask (last two tiles only) ----
    if (kt >= 2 * qblk) {
      const int kbase = kt * BK;
#pragma unroll
      for (int j = 0; j < 32; j++)
        if (kbase + j > qg) s[j] = -1e30f;
    }

    // ---- thread-local online softmax ----
    float t16[16];
#pragma unroll
    for (int j = 0; j < 16; j++) t16[j] = fmaxf(s[j], s[j + 16]);
#pragma unroll
    for (int j = 0; j < 8; j++) t16[j] = fmaxf(t16[j], t16[j + 8]);
#pragma unroll
    for (int j = 0; j < 4; j++) t16[j] = fmaxf(t16[j], t16[j + 4]);
    float vmax = fmaxf(fmaxf(t16[0], t16[1]), fmaxf(t16[2], t16[3]));

    float mn = fmaxf(m, vmax);
    float al = __expf(m - mn);
#pragma unroll
    for (int j = 0; j < 32; j++) s[j] = __expf(s[j] - mn);
    float s0 = 0.f, s1 = 0.f, s2 = 0.f, s3 = 0.f;
#pragma unroll
    for (int j = 0; j < 32; j += 4) {
      s0 += s[j]; s1 += s[j + 1]; s2 += s[j + 2]; s3 += s[j + 3];
    }
    l = l * al + ((s0 + s1) + (s2 + s3));
    m = mn;

    // ---- rescale O ----
#pragma unroll
    for (int i = 0; i < 32; i++) o[i] *= al;

    // ---- O += P . V (broadcast V chunk loads) ----
#pragma unroll 4
    for (int j = 0; j < 32; j++) {
      const float p = s[j];
#pragma unroll
      for (int t = 0; t < 8; t++) {
        float4 v = *(const float4*)&Vb[j * RSTR + 4 * t];
        o[4 * t + 0] += p * v.x;
        o[4 * t + 1] += p * v.y;
        o[4 * t + 2] += p * v.z;
        o[4 * t + 3] += p * v.w;
      }
    }
  }

  // ---- epilogue ----
  const float inv = 1.f / l;
  float* orow = out + ((size_t)b * TT + qg) * DD + 32 * c;
#pragma unroll
  for (int t = 0; t < 8; t++) {
    float4 v = make_float4(o[4 * t + 0] * inv, o[4 * t + 1] * inv,
                           o[4 * t + 2] * inv, o[4 * t + 3] * inv);
    *(float4*)&orow[4 * t] = v;
  }
}

// ---------------------------------------------------------------------------
extern "C" void kernel_launch(void* const* d_in, const int* in_sizes, int n_in,
                              void* d_out, int out_size) {
  const float* X = (const float*)d_in[0];
  const float* Wq = (const float*)d_in[1];
  const float* Wk = (const float*)d_in[2];
  const float* Wv = (const float*)d_in[3];
  float* out = (float*)d_out;

  qkv_gemm_kernel<<<dim3(128, 3), 256>>>(X, Wq, Wk, Wv);

  cudaFuncSetAttribute((const void*)attn_kernel,
                       cudaFuncAttributeMaxDynamicSharedMemorySize, ATT_SMEM);
  attn_kernel<<<dim3(32, BATCHN), 256, ATT_SMEM>>>(out);
}